// round 3
// baseline (speedup 1.0000x reference)
#include <cuda_runtime.h>
#include <math.h>
#include <stdint.h>

#define N_ROWS 8192
#define M_ROWS 8192
#define H_DIM  512

// Scratch (static device globals: allowed; no cudaMalloc anywhere)
__device__ float g_q[(size_t)N_ROWS * H_DIM];
__device__ float g_k[(size_t)M_ROWS * H_DIM];
__device__ float g_S[(size_t)N_ROWS * M_ROWS];
__device__ float g_rowsum[N_ROWS];

// ---------------------------------------------------------------------------
// GEMM NT: C[m,n] = sum_k A[m,k] * B[n,k] (+ bias[n])
// A: [M,K] row-major, B: [N,K] row-major. M,N multiples of 128, K multiple of 8.
// 128x128 block tile, 8x8 per-thread microtile, 256 threads.
// ---------------------------------------------------------------------------
__global__ void __launch_bounds__(256) gemm_nt_kernel(
    const float* __restrict__ A, const float* __restrict__ B,
    const float* __restrict__ bias, float* __restrict__ C,
    int M, int N, int K)
{
    __shared__ float As[8][128];
    __shared__ float Bs[8][128];

    const int tid = threadIdx.x;
    const int tx = tid & 15;   // N direction (8 cols each)
    const int ty = tid >> 4;   // M direction (8 rows each)
    const int m0 = blockIdx.y * 128;
    const int n0 = blockIdx.x * 128;

    // tile-load mapping: each thread loads one float4 from A and one from B
    const int lr = tid >> 1;          // row within 128-tile
    const int lk = (tid & 1) * 4;     // k offset 0 or 4

    const float* Aptr = A + (size_t)(m0 + lr) * K + lk;
    const float* Bptr = B + (size_t)(n0 + lr) * K + lk;

    float acc[8][8];
#pragma unroll
    for (int i = 0; i < 8; i++)
#pragma unroll
        for (int j = 0; j < 8; j++) acc[i][j] = 0.0f;

    for (int k0 = 0; k0 < K; k0 += 8) {
        float4 av = *(const float4*)(Aptr + k0);
        float4 bv = *(const float4*)(Bptr + k0);
        As[lk + 0][lr] = av.x; As[lk + 1][lr] = av.y;
        As[lk + 2][lr] = av.z; As[lk + 3][lr] = av.w;
        Bs[lk + 0][lr] = bv.x; Bs[lk + 1][lr] = bv.y;
        Bs[lk + 2][lr] = bv.z; Bs[lk + 3][lr] = bv.w;
        __syncthreads();

#pragma unroll
        for (int kk = 0; kk < 8; kk++) {
            float a[8], b[8];
#pragma unroll
            for (int i = 0; i < 8; i++) a[i] = As[kk][ty * 8 + i];
#pragma unroll
            for (int j = 0; j < 8; j++) b[j] = Bs[kk][tx * 8 + j];
#pragma unroll
            for (int i = 0; i < 8; i++)
#pragma unroll
                for (int j = 0; j < 8; j++)
                    acc[i][j] = fmaf(a[i], b[j], acc[i][j]);
        }
        __syncthreads();
    }

#pragma unroll
    for (int i = 0; i < 8; i++) {
        const int m = m0 + ty * 8 + i;
        float* Crow = C + (size_t)m * N + n0 + tx * 8;
#pragma unroll
        for (int j = 0; j < 8; j++) {
            float v = acc[i][j];
            if (bias) v += bias[n0 + tx * 8 + j];
            Crow[j] = v;
        }
    }
}

// ---------------------------------------------------------------------------
// Row softmax (exp phase): S[row,:] <- exp(S[row,:] - rowmax); rowsum[row] = sum
// Normalization is folded into the final GEMM epilogue.
// ---------------------------------------------------------------------------
__global__ void __launch_bounds__(256) softmax_exp_kernel(
    float* __restrict__ S, float* __restrict__ rowsum, int cols)
{
    const int row = blockIdx.x;
    float* Srow = S + (size_t)row * cols;
    float4* S4 = (float4*)Srow;
    const int cols4 = cols >> 2;
    const int tid = threadIdx.x;

    __shared__ float red[256];

    float mx = -INFINITY;
    for (int c = tid; c < cols4; c += 256) {
        float4 v = S4[c];
        mx = fmaxf(mx, fmaxf(fmaxf(v.x, v.y), fmaxf(v.z, v.w)));
    }
    red[tid] = mx;
    __syncthreads();
#pragma unroll
    for (int s = 128; s > 0; s >>= 1) {
        if (tid < s) red[tid] = fmaxf(red[tid], red[tid + s]);
        __syncthreads();
    }
    mx = red[0];
    __syncthreads();

    float sum = 0.0f;
    for (int c = tid; c < cols4; c += 256) {
        float4 v = S4[c];
        v.x = expf(v.x - mx);
        v.y = expf(v.y - mx);
        v.z = expf(v.z - mx);
        v.w = expf(v.w - mx);
        sum += v.x + v.y + v.z + v.w;
        S4[c] = v;
    }
    red[tid] = sum;
    __syncthreads();
#pragma unroll
    for (int s = 128; s > 0; s >>= 1) {
        if (tid < s) red[tid] += red[tid + s];
        __syncthreads();
    }
    if (tid == 0) rowsum[row] = red[0];
}

// ---------------------------------------------------------------------------
// GEMM NN + epilogue:
//   out[m,n] = 0.5*features[m,n] + 0.5 * (sum_k P[m,k]*B[k,n]) / rowsum[m]
// P: [M,K] row-major (exp'd scores), B: [K,N] row-major (memory_features).
// ---------------------------------------------------------------------------
__global__ void __launch_bounds__(256) gemm_nn_epilogue_kernel(
    const float* __restrict__ P, const float* __restrict__ B,
    const float* __restrict__ rowsum, const float* __restrict__ features,
    float* __restrict__ out,
    int M, int N, int K)
{
    __shared__ float As[8][128];
    __shared__ float Bs[8][128];

    const int tid = threadIdx.x;
    const int tx = tid & 15;
    const int ty = tid >> 4;
    const int m0 = blockIdx.y * 128;
    const int n0 = blockIdx.x * 128;

    const int lrA = tid >> 1;
    const int lkA = (tid & 1) * 4;
    const int lkB = tid >> 5;          // 0..7
    const int lnB = (tid & 31) * 4;    // 0..124

    const float* Aptr = P + (size_t)(m0 + lrA) * K + lkA;
    const float* Bptr = B + n0 + lnB;

    float acc[8][8];
#pragma unroll
    for (int i = 0; i < 8; i++)
#pragma unroll
        for (int j = 0; j < 8; j++) acc[i][j] = 0.0f;

    for (int k0 = 0; k0 < K; k0 += 8) {
        float4 av = *(const float4*)(Aptr + k0);
        As[lkA + 0][lrA] = av.x; As[lkA + 1][lrA] = av.y;
        As[lkA + 2][lrA] = av.z; As[lkA + 3][lrA] = av.w;
        float4 bv = *(const float4*)(Bptr + (size_t)(k0 + lkB) * N);
        *(float4*)&Bs[lkB][lnB] = bv;
        __syncthreads();

#pragma unroll
        for (int kk = 0; kk < 8; kk++) {
            float a[8], b[8];
#pragma unroll
            for (int i = 0; i < 8; i++) a[i] = As[kk][ty * 8 + i];
#pragma unroll
            for (int j = 0; j < 8; j++) b[j] = Bs[kk][tx * 8 + j];
#pragma unroll
            for (int i = 0; i < 8; i++)
#pragma unroll
                for (int j = 0; j < 8; j++)
                    acc[i][j] = fmaf(a[i], b[j], acc[i][j]);
        }
        __syncthreads();
    }

#pragma unroll
    for (int i = 0; i < 8; i++) {
        const int m = m0 + ty * 8 + i;
        const float scale = 0.5f / rowsum[m];
        const float* Frow = features + (size_t)m * N + n0 + tx * 8;
        float* Orow = out + (size_t)m * N + n0 + tx * 8;
#pragma unroll
        for (int j = 0; j < 8; j++) {
            Orow[j] = 0.5f * Frow[j] + acc[i][j] * scale;
        }
    }
}

// ---------------------------------------------------------------------------
// Launch
// ---------------------------------------------------------------------------
extern "C" void kernel_launch(void* const* d_in, const int* in_sizes, int n_in,
                              void* d_out, int out_size)
{
    (void)in_sizes; (void)n_in; (void)out_size;
    const float* features = (const float*)d_in[0];   // [N, H]
    const float* memf     = (const float*)d_in[1];   // [M, H]
    const float* Wq       = (const float*)d_in[2];   // [H, H]
    const float* bq       = (const float*)d_in[3];   // [H]
    const float* Wk       = (const float*)d_in[4];   // [H, H]
    const float* bk       = (const float*)d_in[5];   // [H]
    float* out = (float*)d_out;                      // [N, H]

    float *q, *k, *S, *rs;
    cudaGetSymbolAddress((void**)&q,  g_q);
    cudaGetSymbolAddress((void**)&k,  g_k);
    cudaGetSymbolAddress((void**)&S,  g_S);
    cudaGetSymbolAddress((void**)&rs, g_rowsum);

    dim3 blk(256);

    // q = features @ Wq^T + bq   [8192,512]
    {
        dim3 grid(H_DIM / 128, N_ROWS / 128);
        gemm_nt_kernel<<<grid, blk>>>(features, Wq, bq, q, N_ROWS, H_DIM, H_DIM);
    }
    // k = memory @ Wk^T + bk     [8192,512]
    {
        dim3 grid(H_DIM / 128, M_ROWS / 128);
        gemm_nt_kernel<<<grid, blk>>>(memf, Wk, bk, k, M_ROWS, H_DIM, H_DIM);
    }
    // S = q @ k^T                [8192,8192]
    {
        dim3 grid(M_ROWS / 128, N_ROWS / 128);
        gemm_nt_kernel<<<grid, blk>>>(q, k, nullptr, S, N_ROWS, M_ROWS, H_DIM);
    }
    // rowwise exp(S - max), rowsum
    softmax_exp_kernel<<<N_ROWS, blk>>>(S, rs, M_ROWS);

    // out = 0.5*features + 0.5*(P @ memf)/rowsum   [8192,512]
    {
        dim3 grid(H_DIM / 128, N_ROWS / 128);
        gemm_nn_epilogue_kernel<<<grid, blk>>>(S, memf, rs, features, out,
                                               N_ROWS, H_DIM, M_ROWS);
    }
}

// round 4
// speedup vs baseline: 1.0751x; 1.0751x over previous
#include <cuda_runtime.h>
#include <math.h>
#include <stdint.h>

#define N_ROWS 8192
#define M_ROWS 8192
#define H_DIM  512

// Scratch (static device globals: allowed; no cudaMalloc anywhere)
__device__ float g_q[(size_t)N_ROWS * H_DIM];
__device__ float g_k[(size_t)M_ROWS * H_DIM];
__device__ float g_S[(size_t)N_ROWS * M_ROWS];
__device__ float g_rowsum[N_ROWS];

// ---------------------------------------------------------------------------
// Packed f32x2 helpers (sm_103a FFMA2 — only reachable via explicit PTX)
// ---------------------------------------------------------------------------
__device__ __forceinline__ unsigned long long pack_dup(float x) {
    unsigned long long r;
    asm("mov.b64 %0, {%1, %1};" : "=l"(r) : "f"(x));
    return r;
}
__device__ __forceinline__ void ffma2(unsigned long long& d,
                                      unsigned long long a,
                                      unsigned long long b) {
    asm("fma.rn.f32x2 %0, %1, %2, %0;" : "+l"(d) : "l"(a), "l"(b));
}
__device__ __forceinline__ float2 unpack2(unsigned long long v) {
    float2 f;
    asm("mov.b64 {%0, %1}, %2;" : "=f"(f.x), "=f"(f.y) : "l"(v));
    return f;
}

// ---------------------------------------------------------------------------
// GEMM NT: C[m,n] = sum_k A[m,k] * B[n,k] (+ bias[n])
// A: [M,K] row-major, B: [N,K] row-major. 128x128 tile, 8x8 microtile,
// 256 threads, inner product in packed f32x2.
// ---------------------------------------------------------------------------
__global__ void __launch_bounds__(256) gemm_nt_kernel(
    const float* __restrict__ A, const float* __restrict__ B,
    const float* __restrict__ bias, float* __restrict__ C,
    int M, int N, int K)
{
    __shared__ float As[8][128];
    __shared__ float Bs[8][128];

    const int tid = threadIdx.x;
    const int tx = tid & 15;   // N direction (8 cols each)
    const int ty = tid >> 4;   // M direction (8 rows each)
    const int m0 = blockIdx.y * 128;
    const int n0 = blockIdx.x * 128;

    const int lr = tid >> 1;          // row within 128-tile
    const int lk = (tid & 1) * 4;     // k offset 0 or 4

    const float* Aptr = A + (size_t)(m0 + lr) * K + lk;
    const float* Bptr = B + (size_t)(n0 + lr) * K + lk;

    unsigned long long acc[8][4];
#pragma unroll
    for (int i = 0; i < 8; i++)
#pragma unroll
        for (int j = 0; j < 4; j++) acc[i][j] = 0ULL;

    for (int k0 = 0; k0 < K; k0 += 8) {
        float4 av = *(const float4*)(Aptr + k0);
        float4 bv = *(const float4*)(Bptr + k0);
        As[lk + 0][lr] = av.x; As[lk + 1][lr] = av.y;
        As[lk + 2][lr] = av.z; As[lk + 3][lr] = av.w;
        Bs[lk + 0][lr] = bv.x; Bs[lk + 1][lr] = bv.y;
        Bs[lk + 2][lr] = bv.z; Bs[lk + 3][lr] = bv.w;
        __syncthreads();

#pragma unroll
        for (int kk = 0; kk < 8; kk++) {
            unsigned long long a2[8], b2[4];
#pragma unroll
            for (int i = 0; i < 8; i++) a2[i] = pack_dup(As[kk][ty * 8 + i]);
#pragma unroll
            for (int j = 0; j < 4; j++)
                b2[j] = *(const unsigned long long*)&Bs[kk][tx * 8 + j * 2];
#pragma unroll
            for (int i = 0; i < 8; i++)
#pragma unroll
                for (int j = 0; j < 4; j++)
                    ffma2(acc[i][j], a2[i], b2[j]);
        }
        __syncthreads();
    }

#pragma unroll
    for (int i = 0; i < 8; i++) {
        const int m = m0 + ty * 8 + i;
        float* Crow = C + (size_t)m * N + n0 + tx * 8;
#pragma unroll
        for (int j = 0; j < 4; j++) {
            float2 v = unpack2(acc[i][j]);
            if (bias) {
                v.x += bias[n0 + tx * 8 + j * 2 + 0];
                v.y += bias[n0 + tx * 8 + j * 2 + 1];
            }
            *(float2*)(Crow + j * 2) = v;
        }
    }
}

// ---------------------------------------------------------------------------
// Row softmax (exp phase): S[row,:] <- exp(S[row,:] - rowmax); rowsum[row]=sum
// Normalization folded into the final GEMM epilogue. DRAM-bound, unchanged.
// ---------------------------------------------------------------------------
__global__ void __launch_bounds__(256) softmax_exp_kernel(
    float* __restrict__ S, float* __restrict__ rowsum, int cols)
{
    const int row = blockIdx.x;
    float* Srow = S + (size_t)row * cols;
    float4* S4 = (float4*)Srow;
    const int cols4 = cols >> 2;
    const int tid = threadIdx.x;

    __shared__ float red[256];

    float mx = -INFINITY;
    for (int c = tid; c < cols4; c += 256) {
        float4 v = S4[c];
        mx = fmaxf(mx, fmaxf(fmaxf(v.x, v.y), fmaxf(v.z, v.w)));
    }
    red[tid] = mx;
    __syncthreads();
#pragma unroll
    for (int s = 128; s > 0; s >>= 1) {
        if (tid < s) red[tid] = fmaxf(red[tid], red[tid + s]);
        __syncthreads();
    }
    mx = red[0];
    __syncthreads();

    float sum = 0.0f;
    for (int c = tid; c < cols4; c += 256) {
        float4 v = S4[c];
        v.x = expf(v.x - mx);
        v.y = expf(v.y - mx);
        v.z = expf(v.z - mx);
        v.w = expf(v.w - mx);
        sum += v.x + v.y + v.z + v.w;
        S4[c] = v;
    }
    red[tid] = sum;
    __syncthreads();
#pragma unroll
    for (int s = 128; s > 0; s >>= 1) {
        if (tid < s) red[tid] += red[tid + s];
        __syncthreads();
    }
    if (tid == 0) rowsum[row] = red[0];
}

// ---------------------------------------------------------------------------
// GEMM NN + epilogue:
//   out[m,n] = 0.5*features[m,n] + 0.5 * (sum_k P[m,k]*B[k,n]) / rowsum[m]
// P: [M,K] row-major (exp'd scores), B: [K,N] row-major (memory_features).
// Inner product in packed f32x2.
// ---------------------------------------------------------------------------
__global__ void __launch_bounds__(256) gemm_nn_epilogue_kernel(
    const float* __restrict__ P, const float* __restrict__ B,
    const float* __restrict__ rowsum, const float* __restrict__ features,
    float* __restrict__ out,
    int M, int N, int K)
{
    __shared__ float As[8][128];
    __shared__ float Bs[8][128];

    const int tid = threadIdx.x;
    const int tx = tid & 15;
    const int ty = tid >> 4;
    const int m0 = blockIdx.y * 128;
    const int n0 = blockIdx.x * 128;

    const int lrA = tid >> 1;
    const int lkA = (tid & 1) * 4;
    const int lkB = tid >> 5;          // 0..7
    const int lnB = (tid & 31) * 4;    // 0..124

    const float* Aptr = P + (size_t)(m0 + lrA) * K + lkA;
    const float* Bptr = B + n0 + lnB;

    unsigned long long acc[8][4];
#pragma unroll
    for (int i = 0; i < 8; i++)
#pragma unroll
        for (int j = 0; j < 4; j++) acc[i][j] = 0ULL;

    for (int k0 = 0; k0 < K; k0 += 8) {
        float4 av = *(const float4*)(Aptr + k0);
        As[lkA + 0][lrA] = av.x; As[lkA + 1][lrA] = av.y;
        As[lkA + 2][lrA] = av.z; As[lkA + 3][lrA] = av.w;
        float4 bv = *(const float4*)(Bptr + (size_t)(k0 + lkB) * N);
        *(float4*)&Bs[lkB][lnB] = bv;
        __syncthreads();

#pragma unroll
        for (int kk = 0; kk < 8; kk++) {
            unsigned long long a2[8], b2[4];
#pragma unroll
            for (int i = 0; i < 8; i++) a2[i] = pack_dup(As[kk][ty * 8 + i]);
#pragma unroll
            for (int j = 0; j < 4; j++)
                b2[j] = *(const unsigned long long*)&Bs[kk][tx * 8 + j * 2];
#pragma unroll
            for (int i = 0; i < 8; i++)
#pragma unroll
                for (int j = 0; j < 4; j++)
                    ffma2(acc[i][j], a2[i], b2[j]);
        }
        __syncthreads();
    }

#pragma unroll
    for (int i = 0; i < 8; i++) {
        const int m = m0 + ty * 8 + i;
        const float scale = 0.5f / rowsum[m];
        const float* Frow = features + (size_t)m * N + n0 + tx * 8;
        float* Orow = out + (size_t)m * N + n0 + tx * 8;
#pragma unroll
        for (int j = 0; j < 4; j++) {
            float2 v = unpack2(acc[i][j]);
            float2 f = *(const float2*)(Frow + j * 2);
            float2 o;
            o.x = 0.5f * f.x + v.x * scale;
            o.y = 0.5f * f.y + v.y * scale;
            *(float2*)(Orow + j * 2) = o;
        }
    }
}

// ---------------------------------------------------------------------------
// Launch
// ---------------------------------------------------------------------------
extern "C" void kernel_launch(void* const* d_in, const int* in_sizes, int n_in,
                              void* d_out, int out_size)
{
    (void)in_sizes; (void)n_in; (void)out_size;
    const float* features = (const float*)d_in[0];   // [N, H]
    const float* memf     = (const float*)d_in[1];   // [M, H]
    const float* Wq       = (const float*)d_in[2];   // [H, H]
    const float* bq       = (const float*)d_in[3];   // [H]
    const float* Wk       = (const float*)d_in[4];   // [H, H]
    const float* bk       = (const float*)d_in[5];   // [H]
    float* out = (float*)d_out;                      // [N, H]

    float *q, *k, *S, *rs;
    cudaGetSymbolAddress((void**)&q,  g_q);
    cudaGetSymbolAddress((void**)&k,  g_k);
    cudaGetSymbolAddress((void**)&S,  g_S);
    cudaGetSymbolAddress((void**)&rs, g_rowsum);

    dim3 blk(256);

    // q = features @ Wq^T + bq   [8192,512]
    {
        dim3 grid(H_DIM / 128, N_ROWS / 128);
        gemm_nt_kernel<<<grid, blk>>>(features, Wq, bq, q, N_ROWS, H_DIM, H_DIM);
    }
    // k = memory @ Wk^T + bk     [8192,512]
    {
        dim3 grid(H_DIM / 128, M_ROWS / 128);
        gemm_nt_kernel<<<grid, blk>>>(memf, Wk, bk, k, M_ROWS, H_DIM, H_DIM);
    }
    // S = q @ k^T                [8192,8192]
    {
        dim3 grid(M_ROWS / 128, N_ROWS / 128);
        gemm_nt_kernel<<<grid, blk>>>(q, k, nullptr, S, N_ROWS, M_ROWS, H_DIM);
    }
    // rowwise exp(S - max), rowsum
    softmax_exp_kernel<<<N_ROWS, blk>>>(S, rs, M_ROWS);

    // out = 0.5*features + 0.5*(P @ memf)/rowsum   [8192,512]
    {
        dim3 grid(H_DIM / 128, N_ROWS / 128);
        gemm_nn_epilogue_kernel<<<grid, blk>>>(S, memf, rs, features, out,
                                               N_ROWS, H_DIM, M_ROWS);
    }
}